// round 6
// baseline (speedup 1.0000x reference)
#include <cuda_runtime.h>
#include <math.h>

// Problem constants (fixed by the dataset)
#define NB   8192      // batch rows
#define NV   32000     // vocab (row length)
#define NK   5         // negatives per row
#define NS   100       // sampling-domain columns of prob
#define EPSF 1e-10f

#define RPB  32                  // rows per block (= one warp per CTA)
#define NCTA (NB / RPB)          // 256 CTAs, all co-resident (2 per SM)

// Scratch for the fused cross-block reduction (no allocs allowed)
__device__ float g_partial[NCTA];
__device__ int   g_ticket = 0;   // re-armed to 0 by the last block each call

// The detached row-max shift cancels exactly in out = terms / sum(terms),
// so no pass over yHat is needed. All gathered operands except the target
// logit live in two 400B windows per row (ind[] < 100):
//   prob[y[b]][0..99]  and  yHat[b][0..99]
// We stage both windows into SMEM with coalesced float4 bursts (1 DRAM
// activate each instead of ~4-5 random sector touches each), then gather
// from SMEM. Only yHat[b][y[b]] stays a random DRAM touch, issued first so
// its latency overlaps the staging loop.
__global__ __launch_bounds__(RPB) void blackout_staged_kernel(
    const float* __restrict__ yHat,
    const float* __restrict__ prob,
    const int*   __restrict__ y,
    const int*   __restrict__ ind,
    float*       __restrict__ out)
{
    __shared__ float s_prob[RPB][NS];   // 12.8 KB
    __shared__ float s_yh[RPB][NS];     // 12.8 KB

    const int lane = threadIdx.x;               // 0..31
    const int b0   = blockIdx.x * RPB;
    const int b    = b0 + lane;                 // this thread's row

    // ---- level 0: coalesced index loads ----
    const int yb = __ldg(&y[b]);                // 128B coalesced per warp
    int id[NK];
    #pragma unroll
    for (int j = 0; j < NK; ++j) id[j] = __ldg(&ind[b * NK + j]); // 640B/warp

    // ---- issue the ONLY truly-random gather early (overlaps staging) ----
    const float tg = __ldg(&yHat[(long long)b * NV + yb]);

    // ---- stage 32x 400B prob rows + 32x 400B yHat heads, coalesced ----
    // Each row: lanes 0..24 load one float4 (25*16B = 400B burst).
    #pragma unroll 4
    for (int r = 0; r < RPB; ++r) {
        const int ybr = __shfl_sync(0xffffffffu, yb, r);
        if (lane < NS / 4) {
            float4 pv = __ldg((const float4*)(prob + (long long)ybr * NS) + lane);
            *(float4*)&s_prob[r][lane * 4] = pv;
            float4 hv = __ldg((const float4*)(yHat + (long long)(b0 + r) * NV) + lane);
            *(float4*)&s_yh[r][lane * 4] = hv;
        }
    }
    __syncthreads();

    // ---- gather from SMEM + compute (max shift cancels in the ratio) ----
    float p[NK], q = INFINITY;
    #pragma unroll
    for (int j = 0; j < NK; ++j) {
        p[j] = 1.0f / s_prob[lane][id[j]];
        q = fminf(q, p[j]);
    }

    float t[NK];
    float t0 = q * expf(tg);
    float S  = t0;
    #pragma unroll
    for (int j = 0; j < NK; ++j) {
        t[j] = p[j] * expf(s_yh[lane][id[j]]);
        S += t[j];
    }
    const float inv = 1.0f / S;

    float acc = logf(t0 * inv + EPSF);          // log(out_0 + eps)
    #pragma unroll
    for (int j = 0; j < NK; ++j)
        acc += logf(1.0f - t[j] * inv + EPSF);  // log(1 - out_j + eps)

    // ---- deterministic warp reduction (32 -> 1) ----
    #pragma unroll
    for (int o = 16; o; o >>= 1) acc += __shfl_xor_sync(0xffffffffu, acc, o);

    __shared__ int s_last;
    if (lane == 0) {
        g_partial[blockIdx.x] = acc;
        __threadfence();                         // publish partial to L2
        int t_ = atomicAdd(&g_ticket, 1);        // ticket: last block finishes
        s_last = (t_ == NCTA - 1);
    }
    __syncthreads();

    if (s_last) {
        // volatile: bypass this SM's (non-coherent) L1 when reading partials
        // produced by other SMs. Fixed order -> deterministic.
        volatile float* gp = g_partial;
        float v = 0.0f;
        #pragma unroll
        for (int k = 0; k < NCTA / RPB; ++k)     // 8 strided reads per lane
            v += gp[k * RPB + lane];
        #pragma unroll
        for (int o = 16; o; o >>= 1) v += __shfl_xor_sync(0xffffffffu, v, o);
        if (lane == 0) {
            out[0] = -v / (float)(NB * (NK + 1));
            g_ticket = 0;                        // re-arm for next graph replay
        }
    }
}

extern "C" void kernel_launch(void* const* d_in, const int* in_sizes, int n_in,
                              void* d_out, int out_size)
{
    const float* yHat = (const float*)d_in[0];   // [8192, 32000] f32
    const float* prob = (const float*)d_in[1];   // [32000, 100] f32
    const int*   y    = (const int*)d_in[2];     // [8192] i32
    const int*   ind  = (const int*)d_in[3];     // [8192, 5] i32
    float* out = (float*)d_out;

    blackout_staged_kernel<<<NCTA, RPB>>>(yHat, prob, y, ind, out);
}

// round 7
// speedup vs baseline: 1.4982x; 1.4982x over previous
#include <cuda_runtime.h>
#include <math.h>

// Problem constants (fixed by the dataset)
#define NB   8192      // batch rows
#define NV   32000     // vocab (row length)
#define NK   5         // negatives per row
#define NS   100       // sampling-domain columns of prob
#define EPSF 1e-10f

#define NCTA 128       // 128 CTAs x 64 threads = 8192 = one thread per row
#define NTHR 64

// Scratch for the fused cross-block reduction (no allocs allowed)
__device__ float g_partial[NCTA];
__device__ int   g_ticket = 0;   // re-armed to 0 by the last block each call

// The detached row-max shift cancels exactly in out = terms / sum(terms),
// so no pass over yHat is needed — just 6 gathered logits per row (ind[] <
// 100, plus the target column y[b]). Pure latency-bound: structure so all
// 11 gathers issue back-to-back (max MLP, no reg cap), then a short
// MUFU-based math tail.
__global__ __launch_bounds__(NTHR, 1) void blackout_fused_kernel(
    const float* __restrict__ yHat,
    const float* __restrict__ prob,
    const int*   __restrict__ y,
    const int*   __restrict__ ind,
    float*       __restrict__ out)
{
    const int b = blockIdx.x * NTHR + threadIdx.x;   // 0..8191, exact cover

    // ---- level 0: coalesced index loads (y, ind are tiny & L2-hot) ----
    const int yb = __ldg(&y[b]);
    int id[NK];
    #pragma unroll
    for (int j = 0; j < NK; ++j) id[j] = __ldg(&ind[b * NK + j]);

    // ---- level 1: ALL 11 data gathers issued before any math ----
    const float* __restrict__ prow = prob + (long long)yb * NS;
    const float* __restrict__ rowf = yHat + (long long)b * NV;

    float pr[NK], cj[NK];
    const float tg = __ldg(&rowf[yb]);            // truly-random target gather
    #pragma unroll
    for (int j = 0; j < NK; ++j) pr[j] = __ldg(&prow[id[j]]);  // prob row (L2-hot)
    #pragma unroll
    for (int j = 0; j < NK; ++j) cj[j] = __ldg(&rowf[id[j]]);  // row head (1 DRAM row)

    // ---- math tail (fast intrinsics; max shift cancels in the ratio) ----
    float p[NK], q = INFINITY;
    #pragma unroll
    for (int j = 0; j < NK; ++j) {
        p[j] = __frcp_rn(pr[j]);
        q = fminf(q, p[j]);
    }

    float t[NK];
    float t0 = q * __expf(tg);
    float S  = t0;
    #pragma unroll
    for (int j = 0; j < NK; ++j) {
        t[j] = p[j] * __expf(cj[j]);
        S += t[j];
    }
    const float inv = 1.0f / S;

    float acc = __logf(t0 * inv + EPSF);          // log(out_0 + eps)
    #pragma unroll
    for (int j = 0; j < NK; ++j)
        acc += __logf(1.0f - t[j] * inv + EPSF);  // log(1 - out_j + eps)

    // ---- deterministic block reduction (64 -> 1) ----
    __shared__ float sw[2];
    #pragma unroll
    for (int o = 16; o; o >>= 1) acc += __shfl_xor_sync(0xffffffffu, acc, o);
    const int lane = threadIdx.x & 31;
    const int wid  = threadIdx.x >> 5;
    if (lane == 0) sw[wid] = acc;
    __syncthreads();

    __shared__ int s_last;
    if (threadIdx.x == 0) {
        g_partial[blockIdx.x] = sw[0] + sw[1];
        __threadfence();                         // publish partial to L2
        int t_ = atomicAdd(&g_ticket, 1);        // last block does the final sum
        s_last = (t_ == NCTA - 1);
    }
    __syncthreads();

    if (s_last && threadIdx.x < 32) {
        // volatile: bypass this SM's (non-coherent) L1 when reading partials
        // produced by other SMs. Fixed order -> deterministic.
        volatile float* gp = g_partial;
        float v = 0.0f;
        #pragma unroll
        for (int k = 0; k < NCTA / 32; ++k)
            v += gp[k * 32 + threadIdx.x];
        #pragma unroll
        for (int o = 16; o; o >>= 1) v += __shfl_xor_sync(0xffffffffu, v, o);
        if (threadIdx.x == 0) {
            out[0] = -v / (float)(NB * (NK + 1));
            g_ticket = 0;                        // re-arm for next graph replay
        }
    }
}

extern "C" void kernel_launch(void* const* d_in, const int* in_sizes, int n_in,
                              void* d_out, int out_size)
{
    const float* yHat = (const float*)d_in[0];   // [8192, 32000] f32
    const float* prob = (const float*)d_in[1];   // [32000, 100] f32
    const int*   y    = (const int*)d_in[2];     // [8192] i32
    const int*   ind  = (const int*)d_in[3];     // [8192, 5] i32
    float* out = (float*)d_out;

    blackout_fused_kernel<<<NCTA, NTHR>>>(yHat, prob, y, ind, out);
}